// round 7
// baseline (speedup 1.0000x reference)
#include <cuda_runtime.h>
#include <math.h>

// ---------------- problem constants ----------------
#define B_ 32
#define T_ 512
#define J_ 64
#define E_ 300
#define H_ 256

static constexpr size_t NCs = 16384;  // B*T
static constexpr size_t NQs = 2048;   // B*J

// ---------------- scratch layout (single __device__ arena) ----------------
static constexpr size_t OFF_CX    = 0;                          // [NC][300]
static constexpr size_t OFF_QX    = OFF_CX   + NCs * 300;       // [NQ][300]
static constexpr size_t OFF_HB    = OFF_QX   + NQs * 300;       // [NC][300]
static constexpr size_t OFF_TB    = OFF_HB   + NCs * 300;       // [NC][300]
static constexpr size_t OFF_CREP  = OFF_TB   + NCs * 300;       // [NC][512]
static constexpr size_t OFF_QREP  = OFF_CREP + NCs * 512;       // [NQ][512]
static constexpr size_t OFF_G     = OFF_QREP + NQs * 512;       // [NC][2048]
static constexpr size_t OFF_MA    = OFF_G    + NCs * 2048;      // [NC][512]
static constexpr size_t OFF_MB    = OFF_MA   + NCs * 512;       // [NC][512]
static constexpr size_t OFF_M2    = OFF_MB   + NCs * 512;       // [NC][512]
static constexpr size_t OFF_GATES = OFF_M2   + NCs * 512;       // [2][NC][1024]
static constexpr size_t OFF_H     = OFF_GATES + 2 * NCs * 1024; // 2 x [2][32][256]
static constexpr size_t OFF_SMAX  = OFF_H    + 2 * 16384;       // [NC]
static constexpr size_t OFF_UW2   = OFF_SMAX + 16384;           // [NQ]
static constexpr size_t OFF_Q2C   = OFF_UW2  + 2048;            // [B][512]
static constexpr size_t SCRATCH_TOTAL = OFF_Q2C + 32 * 512;

__device__ float g_scratch[SCRATCH_TOTAL];
__device__ unsigned g_barcnt;

__device__ __forceinline__ float sigmoidf_(float x) { return 1.f / (1.f + expf(-x)); }

// ---------------- embedding gather ----------------
__global__ void __launch_bounds__(256) gather_embed(
    const int* __restrict__ tok, const float* __restrict__ emb,
    float* __restrict__ out, int nrows)
{
    int idx = blockIdx.x * 256 + threadIdx.x;
    int total = nrows * E_;
    if (idx >= total) return;
    int r = idx / E_;
    int e = idx - r * E_;
    out[idx] = emb[(size_t)tok[r] * E_ + e];
}

// ---------------- highway combine: x = h*t + (1-t)*x ----------------
__global__ void __launch_bounds__(256) hw_combine(
    float* __restrict__ x, const float* __restrict__ h,
    const float* __restrict__ t, int n)
{
    int i = blockIdx.x * 256 + threadIdx.x;
    if (i < n) { float tv = t[i]; x[i] = h[i] * tv + (1.f - tv) * x[i]; }
}

// ---------------- SGEMM: C[M,N] = A[M,K] @ B[N,K]^T (+bias1+bias2, opt relu) ----------------
__global__ void __launch_bounds__(256) sgemm_tn(
    const float* __restrict__ A, const float* __restrict__ Bm,
    float* __restrict__ C,
    const float* __restrict__ bias1, const float* __restrict__ bias2,
    int M, int N, int K, int relu)
{
    __shared__ float As[8][132];
    __shared__ float Bs[8][132];
    const int tid = threadIdx.x;
    const int bm = blockIdx.y * 128, bn = blockIdx.x * 128;
    const int lr = tid >> 1;
    const int lc = (tid & 1) << 2;
    const int tr = (tid >> 4) << 3;
    const int tc = (tid & 15) << 3;
    float acc[8][8];
#pragma unroll
    for (int i = 0; i < 8; i++)
#pragma unroll
        for (int j = 0; j < 8; j++) acc[i][j] = 0.f;

    for (int k0 = 0; k0 < K; k0 += 8) {
        float4 a4 = make_float4(0.f, 0.f, 0.f, 0.f);
        float4 b4 = make_float4(0.f, 0.f, 0.f, 0.f);
        if (bm + lr < M && k0 + lc < K)
            a4 = *(const float4*)(A + (size_t)(bm + lr) * K + k0 + lc);
        if (bn + lr < N && k0 + lc < K)
            b4 = *(const float4*)(Bm + (size_t)(bn + lr) * K + k0 + lc);
        __syncthreads();
        As[lc + 0][lr] = a4.x; As[lc + 1][lr] = a4.y;
        As[lc + 2][lr] = a4.z; As[lc + 3][lr] = a4.w;
        Bs[lc + 0][lr] = b4.x; Bs[lc + 1][lr] = b4.y;
        Bs[lc + 2][lr] = b4.z; Bs[lc + 3][lr] = b4.w;
        __syncthreads();
#pragma unroll
        for (int kk = 0; kk < 8; kk++) {
            float ar[8], br[8];
            *(float4*)(ar)     = *(const float4*)(&As[kk][tr]);
            *(float4*)(ar + 4) = *(const float4*)(&As[kk][tr + 4]);
            *(float4*)(br)     = *(const float4*)(&Bs[kk][tc]);
            *(float4*)(br + 4) = *(const float4*)(&Bs[kk][tc + 4]);
#pragma unroll
            for (int i = 0; i < 8; i++)
#pragma unroll
                for (int j = 0; j < 8; j++) acc[i][j] += ar[i] * br[j];
        }
    }
#pragma unroll
    for (int i = 0; i < 8; i++) {
        int row = bm + tr + i;
        if (row >= M) continue;
#pragma unroll
        for (int j = 0; j < 8; j++) {
            int col = bn + tc + j;
            if (col >= N) continue;
            float v = acc[i][j];
            if (bias1) v += bias1[col];
            if (bias2) v += bias2[col];
            if (relu) v = fmaxf(v, 0.f);
            C[(size_t)row * N + col] = v;
        }
    }
}

// ---------------- persistent biLSTM recurrence ----------------
// 64 blocks (32 unit-slices x 2 dirs), 256 threads, ALL co-resident -> spin
// grid-barrier is deadlock-free. One barrier per step; h double-buffered in
// global; c lives in a register. Weights stay L1-resident across all steps.
__global__ void reset_bar() { g_barcnt = 0u; }

__global__ void __launch_bounds__(256) lstm_persist(
    const float* __restrict__ gates, const float* __restrict__ whh,
    float* __restrict__ hbuf,   // 2 buffers of [2][32][256]
    float* __restrict__ rep, int T)
{
    __shared__ float sh[256 * 33];   // h_prev (this dir), k-major, padded
    const int tid = threadIdx.x;
    const int d    = blockIdx.x >> 5;        // direction
    const int ublk = blockIdx.x & 31;        // unit slice
    const int u  = (ublk << 3) + (tid >> 5); // hidden unit 0..255
    const int bb = tid & 31;                 // batch
    const int hc_idx = (d * 32 + bb) * 256 + u;

    const float4* w0 = (const float4*)(whh + ((size_t)d * 1024 +        u) * 256);
    const float4* w1 = (const float4*)(whh + ((size_t)d * 1024 + 256  + u) * 256);
    const float4* w2 = (const float4*)(whh + ((size_t)d * 1024 + 512  + u) * 256);
    const float4* w3 = (const float4*)(whh + ((size_t)d * 1024 + 768  + u) * 256);

    float cc = 0.f;   // cell state, thread-private across steps

    for (int s = 0; s < T; s++) {
        const float* hprev = hbuf + (size_t)(s & 1) * 16384;
        float* hnext       = hbuf + (size_t)((s & 1) ^ 1) * 16384;

        if (s == 0) {
            for (int idx = tid; idx < 32 * 256; idx += 256) {
                int b = idx >> 8, k = idx & 255;
                sh[k * 33 + b] = 0.f;
            }
        } else {
            for (int idx = tid; idx < 32 * 256; idx += 256) {
                int b = idx >> 8, k = idx & 255;
                sh[k * 33 + b] = hprev[(d * 32 + b) * 256 + k];
            }
        }
        __syncthreads();

        float a0 = 0.f, a1 = 0.f, a2 = 0.f, a3 = 0.f;
#pragma unroll 4
        for (int k4 = 0; k4 < 64; k4++) {
            float4 wa = w0[k4], wb = w1[k4], wc = w2[k4], wd = w3[k4];
            const float* hp = &sh[(k4 << 2) * 33 + bb];
            float h0 = hp[0], h1 = hp[33], h2 = hp[66], h3 = hp[99];
            a0 += wa.x * h0 + wa.y * h1 + wa.z * h2 + wa.w * h3;
            a1 += wb.x * h0 + wb.y * h1 + wb.z * h2 + wb.w * h3;
            a2 += wc.x * h0 + wc.y * h1 + wc.z * h2 + wc.w * h3;
            a3 += wd.x * h0 + wd.y * h1 + wd.z * h2 + wd.w * h3;
        }

        const int t = (d == 0) ? s : (T - 1 - s);
        const int row = bb * T + t;
        const size_t gb = ((size_t)d * 32 * T + row) * 1024 + u;
        float xi = gates[gb]       + a0;
        float xf = gates[gb + 256] + a1;
        float xg = gates[gb + 512] + a2;
        float xo = gates[gb + 768] + a3;
        float ig = sigmoidf_(xi), fg = sigmoidf_(xf), og = sigmoidf_(xo);
        float gg = tanhf(xg);
        float cn = fg * cc + ig * gg;
        cc = cn;
        float hn = og * tanhf(cn);
        hnext[hc_idx] = hn;
        rep[(size_t)row * 512 + (d << 8) + u] = hn;

        // ---- grid barrier (release write -> arrive -> spin -> acquire) ----
        __syncthreads();
        if (tid == 0) {
            __threadfence();
            unsigned target = 64u * (unsigned)(s + 1);
            atomicAdd(&g_barcnt, 1u);
            while (*((volatile unsigned*)&g_barcnt) < target) { __nanosleep(20); }
            __threadfence();
        }
        __syncthreads();
    }
}

// ---------------- attention: uw2[r] = dot(U[r], w2) ----------------
__global__ void __launch_bounds__(256) uw2_kernel(
    const float* __restrict__ U, const float* __restrict__ attw, float* __restrict__ uw2)
{
    int w = threadIdx.x >> 5, lane = threadIdx.x & 31;
    int row = blockIdx.x * 8 + w;
    const float* w2 = attw + 512;
    float acc = 0.f;
    const float* u = U + (size_t)row * 512;
    for (int i = lane; i < 512; i += 32) acc += u[i] * w2[i];
#pragma unroll
    for (int o = 16; o; o >>= 1) acc += __shfl_xor_sync(0xffffffffu, acc, o);
    if (lane == 0) uw2[row] = acc;
}

// ---------------- attention main ----------------
__global__ void __launch_bounds__(256) attn_s(
    const float* __restrict__ Hc, const float* __restrict__ U,
    const float* __restrict__ attw, const float* __restrict__ attb,
    const float* __restrict__ uw2, float* __restrict__ G, float* __restrict__ Smax)
{
    __shared__ float hc[512], hw3[512], sS[64], wsum[8];
    __shared__ float sHw1, sMx, sSum;
    const int row = blockIdx.x;
    const int b = row >> 9;
    const int tid = threadIdx.x;
    const float* w1 = attw;
    const float* w3 = attw + 1024;
    float p0 = 0.f;
    for (int i = tid; i < 512; i += 256) {
        float v = Hc[(size_t)row * 512 + i];
        hc[i] = v; hw3[i] = v * w3[i];
        p0 += v * w1[i];
    }
#pragma unroll
    for (int o = 16; o; o >>= 1) p0 += __shfl_xor_sync(0xffffffffu, p0, o);
    int w = tid >> 5, lane = tid & 31;
    if (lane == 0) wsum[w] = p0;
    __syncthreads();
    if (tid == 0) {
        float s = 0.f;
        for (int i = 0; i < 8; i++) s += wsum[i];
        sHw1 = s;
    }
    __syncthreads();
    float bval = attb[0];
    for (int jj = 0; jj < 8; jj++) {
        int j = w * 8 + jj;
        const float* u = U + ((size_t)(b * 64 + j)) * 512;
        float acc = 0.f;
        for (int k = lane; k < 512; k += 32) acc += hw3[k] * u[k];
#pragma unroll
        for (int o = 16; o; o >>= 1) acc += __shfl_xor_sync(0xffffffffu, acc, o);
        if (lane == 0) sS[j] = sHw1 + uw2[b * 64 + j] + acc + bval;
    }
    __syncthreads();
    if (tid == 0) {
        float mx = -1e30f;
        for (int j = 0; j < 64; j++) mx = fmaxf(mx, sS[j]);
        float sm = 0.f;
        for (int j = 0; j < 64; j++) sm += expf(sS[j] - mx);
        sMx = mx; sSum = sm;
        Smax[row] = mx;
    }
    __syncthreads();
    if (tid < 64) sS[tid] = expf(sS[tid] - sMx) / sSum;
    __syncthreads();
    for (int half = 0; half < 2; half++) {
        int dc = tid + half * 256;
        float acc = 0.f;
        for (int j = 0; j < 64; j++)
            acc += sS[j] * U[((size_t)(b * 64 + j)) * 512 + dc];
        float hv = hc[dc];
        G[(size_t)row * 2048 + dc]        = hv;
        G[(size_t)row * 2048 + 512  + dc] = acc;
        G[(size_t)row * 2048 + 1024 + dc] = hv * acc;
    }
}

// ---------------- q2c ----------------
__global__ void __launch_bounds__(256) attn_q2c(
    const float* __restrict__ Smax, const float* __restrict__ Hc, float* __restrict__ q2c)
{
    __shared__ float p[512];
    __shared__ float sMx, sSum;
    const int b = blockIdx.x, tid = threadIdx.x;
    for (int i = tid; i < 512; i += 256) p[i] = Smax[b * 512 + i];
    __syncthreads();
    if (tid == 0) {
        float mx = -1e30f;
        for (int t = 0; t < 512; t++) mx = fmaxf(mx, p[t]);
        float sm = 0.f;
        for (int t = 0; t < 512; t++) sm += expf(p[t] - mx);
        sMx = mx; sSum = sm;
    }
    __syncthreads();
    for (int i = tid; i < 512; i += 256) p[i] = expf(p[i] - sMx) / sSum;
    __syncthreads();
    for (int half = 0; half < 2; half++) {
        int dc = tid + half * 256;
        float acc = 0.f;
        for (int t = 0; t < 512; t++)
            acc += p[t] * Hc[((size_t)(b * 512 + t)) * 512 + dc];
        q2c[b * 512 + dc] = acc;
    }
}

// ---------------- G[:,1536:2048] = Hc * q2c[b] ----------------
__global__ void __launch_bounds__(256) g4_kernel(
    const float* __restrict__ Hc, const float* __restrict__ q2c, float* __restrict__ G)
{
    int idx = blockIdx.x * 256 + threadIdx.x;
    if (idx >= (int)(NCs * 512)) return;
    int row = idx >> 9, dc = idx & 511;
    int b = row >> 9;
    G[(size_t)row * 2048 + 1536 + dc] = Hc[idx] * q2c[(b << 9) + dc];
}

// ---------------- final logits ----------------
__global__ void __launch_bounds__(256) final_dot(
    const float* __restrict__ G, const float* __restrict__ M,
    const float* __restrict__ pw, const float* __restrict__ pb,
    float* __restrict__ out)
{
    int w = threadIdx.x >> 5, lane = threadIdx.x & 31;
    int row = blockIdx.x * 8 + w;
    float acc = 0.f;
    const float* g = G + (size_t)row * 2048;
    for (int i = lane; i < 2048; i += 32) acc += g[i] * pw[i];
    const float* m = M + (size_t)row * 512;
    for (int i = lane; i < 512; i += 32) acc += m[i] * pw[2048 + i];
#pragma unroll
    for (int o = 16; o; o >>= 1) acc += __shfl_xor_sync(0xffffffffu, acc, o);
    if (lane == 0) out[row] = acc + pb[0];
}

// ---------------- host orchestration ----------------
static inline void launch_sgemm(const float* A, const float* Bm, float* C,
                                const float* b1, const float* b2,
                                int M, int N, int K, int relu)
{
    dim3 grid((N + 127) / 128, (M + 127) / 128);
    sgemm_tn<<<grid, 256>>>(A, Bm, C, b1, b2, M, N, K, relu);
}

extern "C" void kernel_launch(void* const* d_in, const int* in_sizes, int n_in,
                              void* d_out, int out_size)
{
    (void)in_sizes; (void)n_in; (void)out_size;
    const int*   qtok      = (const int*)d_in[0];
    const int*   ctok      = (const int*)d_in[1];
    const float* emb       = (const float*)d_in[2];
    const float* hw_lin_w  = (const float*)d_in[3];
    const float* hw_lin_b  = (const float*)d_in[4];
    const float* hw_gate_w = (const float*)d_in[5];
    const float* hw_gate_b = (const float*)d_in[6];
    const float* ctx_wih   = (const float*)d_in[7];
    const float* ctx_whh   = (const float*)d_in[8];
    const float* ctx_bih   = (const float*)d_in[9];
    const float* ctx_bhh   = (const float*)d_in[10];
    const float* mod1_wih  = (const float*)d_in[11];
    const float* mod1_whh  = (const float*)d_in[12];
    const float* mod1_bih  = (const float*)d_in[13];
    const float* mod1_bhh  = (const float*)d_in[14];
    const float* mod2_wih  = (const float*)d_in[15];
    const float* mod2_whh  = (const float*)d_in[16];
    const float* mod2_bih  = (const float*)d_in[17];
    const float* mod2_bhh  = (const float*)d_in[18];
    const float* dec_wih   = (const float*)d_in[19];
    const float* dec_whh   = (const float*)d_in[20];
    const float* dec_bih   = (const float*)d_in[21];
    const float* dec_bhh   = (const float*)d_in[22];
    const float* att_w     = (const float*)d_in[23];
    const float* att_b     = (const float*)d_in[24];
    const float* p1_w      = (const float*)d_in[25];
    const float* p1_b      = (const float*)d_in[26];
    const float* p2_w      = (const float*)d_in[27];
    const float* p2_b      = (const float*)d_in[28];
    float* out = (float*)d_out;

    float* S = nullptr;
    cudaGetSymbolAddress((void**)&S, g_scratch);
    float* cx    = S + OFF_CX;
    float* qx    = S + OFF_QX;
    float* hb    = S + OFF_HB;
    float* tb    = S + OFF_TB;
    float* crep  = S + OFF_CREP;
    float* qrep  = S + OFF_QREP;
    float* Gb    = S + OFF_G;
    float* Ma    = S + OFF_MA;
    float* Mb    = S + OFF_MB;
    float* M2b   = S + OFF_M2;
    float* gates = S + OFF_GATES;
    float* Hbuf  = S + OFF_H;
    float* smax  = S + OFF_SMAX;
    float* uw2b  = S + OFF_UW2;
    float* q2cb  = S + OFF_Q2C;

    const int NC = (int)NCs;
    const int NQ = (int)NQs;

    // 1. embedding gather
    gather_embed<<<(NC * E_ + 255) / 256, 256>>>(ctok, emb, cx, NC);
    gather_embed<<<(NQ * E_ + 255) / 256, 256>>>(qtok, emb, qx, NQ);

    // 2. highway (2 layers), context then question
    for (int l = 0; l < 2; l++) {
        launch_sgemm(cx, hw_lin_w + (size_t)l * E_ * E_, hb, hw_lin_b + l * E_, nullptr, NC, E_, E_, 1);
        launch_sgemm(cx, hw_gate_w + (size_t)l * E_ * E_, tb, hw_gate_b + l * E_, nullptr, NC, E_, E_, 1);
        hw_combine<<<(NC * E_ + 255) / 256, 256>>>(cx, hb, tb, NC * E_);
    }
    for (int l = 0; l < 2; l++) {
        launch_sgemm(qx, hw_lin_w + (size_t)l * E_ * E_, hb, hw_lin_b + l * E_, nullptr, NQ, E_, E_, 1);
        launch_sgemm(qx, hw_gate_w + (size_t)l * E_ * E_, tb, hw_gate_b + l * E_, nullptr, NQ, E_, E_, 1);
        hw_combine<<<(NQ * E_ + 255) / 256, 256>>>(qx, hb, tb, NQ * E_);
    }

    // helper macro: one biLSTM = 2 gate GEMMs + 1 persistent recurrence kernel
    #define RUN_BILSTM(Xin, WIH, WHH, BIH, BHH, KDIM, ROWS, TLEN, REP)                         \
        do {                                                                                   \
            for (int d = 0; d < 2; d++)                                                        \
                launch_sgemm((Xin), (WIH) + (size_t)d * 1024 * (KDIM),                         \
                             gates + (size_t)d * (ROWS) * 1024,                                \
                             (BIH) + d * 1024, (BHH) + d * 1024, (ROWS), 1024, (KDIM), 0);     \
            reset_bar<<<1, 1>>>();                                                             \
            lstm_persist<<<64, 256>>>(gates, (WHH), Hbuf, (REP), (TLEN));                      \
        } while (0)

    // 3. contextual biLSTM
    RUN_BILSTM(cx, ctx_wih, ctx_whh, ctx_bih, ctx_bhh, E_, NC, T_, crep);
    RUN_BILSTM(qx, ctx_wih, ctx_whh, ctx_bih, ctx_bhh, E_, NQ, J_, qrep);

    // 4. attention -> G
    uw2_kernel<<<NQ / 8, 256>>>(qrep, att_w, uw2b);
    attn_s<<<NC, 256>>>(crep, qrep, att_w, att_b, uw2b, Gb, smax);
    attn_q2c<<<B_, 256>>>(smax, crep, q2cb);
    g4_kernel<<<(NC * 512 + 255) / 256, 256>>>(crep, q2cb, Gb);

    // 5. modeling biLSTMs
    RUN_BILSTM(Gb, mod1_wih, mod1_whh, mod1_bih, mod1_bhh, 2048, NC, T_, Ma);
    RUN_BILSTM(Ma, mod2_wih, mod2_whh, mod2_bih, mod2_bhh, 512, NC, T_, Mb);

    // 6. start logits
    final_dot<<<NC / 8, 256>>>(Gb, Mb, p1_w, p1_b, out);

    // 7. decode biLSTM + end logits
    RUN_BILSTM(Mb, dec_wih, dec_whh, dec_bih, dec_bhh, 512, NC, T_, M2b);
    final_dot<<<NC / 8, 256>>>(Gb, M2b, p2_w, p2_b, out + NC);

    #undef RUN_BILSTM
}

// round 8
// speedup vs baseline: 1.0583x; 1.0583x over previous
#include <cuda_runtime.h>
#include <math.h>

// ---------------- problem constants ----------------
#define B_ 32
#define T_ 512
#define J_ 64
#define E_ 300
#define H_ 256

static constexpr size_t NCs = 16384;  // B*T
static constexpr size_t NQs = 2048;   // B*J

// ---------------- scratch layout (single __device__ arena) ----------------
static constexpr size_t OFF_CX    = 0;                          // [NC][300]
static constexpr size_t OFF_QX    = OFF_CX   + NCs * 300;       // [NQ][300]
static constexpr size_t OFF_HB    = OFF_QX   + NQs * 300;       // [NC][300]
static constexpr size_t OFF_TB    = OFF_HB   + NCs * 300;       // [NC][300]
static constexpr size_t OFF_CREP  = OFF_TB   + NCs * 300;       // [NC][512]
static constexpr size_t OFF_QREP  = OFF_CREP + NCs * 512;       // [NQ][512]
static constexpr size_t OFF_G     = OFF_QREP + NQs * 512;       // [NC][2048]
static constexpr size_t OFF_MA    = OFF_G    + NCs * 2048;      // [NC][512]
static constexpr size_t OFF_MB    = OFF_MA   + NCs * 512;       // [NC][512]
static constexpr size_t OFF_M2    = OFF_MB   + NCs * 512;       // [NC][512]
static constexpr size_t OFF_GATES = OFF_M2   + NCs * 512;       // [2][NC][1024] (GEMM out)
static constexpr size_t OFF_GT    = OFF_GATES + 2 * NCs * 1024; // [2][T][1024][32] transposed
static constexpr size_t OFF_H     = OFF_GT   + 2 * NCs * 1024;  // 2 x [2][256][32]
static constexpr size_t OFF_SMAX  = OFF_H    + 2 * 16384;       // [NC]
static constexpr size_t OFF_UW2   = OFF_SMAX + 16384;           // [NQ]
static constexpr size_t OFF_Q2C   = OFF_UW2  + 2048;            // [B][512]
static constexpr size_t SCRATCH_TOTAL = OFF_Q2C + 32 * 512;

__device__ float g_scratch[SCRATCH_TOTAL];
__device__ unsigned g_barcnt2[2];

__device__ __forceinline__ float sigmoidf_(float x) { return 1.f / (1.f + expf(-x)); }

// ---------------- embedding gather ----------------
__global__ void __launch_bounds__(256) gather_embed(
    const int* __restrict__ tok, const float* __restrict__ emb,
    float* __restrict__ out, int nrows)
{
    int idx = blockIdx.x * 256 + threadIdx.x;
    int total = nrows * E_;
    if (idx >= total) return;
    int r = idx / E_;
    int e = idx - r * E_;
    out[idx] = emb[(size_t)tok[r] * E_ + e];
}

// ---------------- highway combine ----------------
__global__ void __launch_bounds__(256) hw_combine(
    float* __restrict__ x, const float* __restrict__ h,
    const float* __restrict__ t, int n)
{
    int i = blockIdx.x * 256 + threadIdx.x;
    if (i < n) { float tv = t[i]; x[i] = h[i] * tv + (1.f - tv) * x[i]; }
}

// ---------------- SGEMM: C[M,N] = A[M,K] @ B[N,K]^T (+bias1+bias2, opt relu) ----------------
__global__ void __launch_bounds__(256) sgemm_tn(
    const float* __restrict__ A, const float* __restrict__ Bm,
    float* __restrict__ C,
    const float* __restrict__ bias1, const float* __restrict__ bias2,
    int M, int N, int K, int relu)
{
    __shared__ float As[8][132];
    __shared__ float Bs[8][132];
    const int tid = threadIdx.x;
    const int bm = blockIdx.y * 128, bn = blockIdx.x * 128;
    const int lr = tid >> 1;
    const int lc = (tid & 1) << 2;
    const int tr = (tid >> 4) << 3;
    const int tc = (tid & 15) << 3;
    float acc[8][8];
#pragma unroll
    for (int i = 0; i < 8; i++)
#pragma unroll
        for (int j = 0; j < 8; j++) acc[i][j] = 0.f;

    for (int k0 = 0; k0 < K; k0 += 8) {
        float4 a4 = make_float4(0.f, 0.f, 0.f, 0.f);
        float4 b4 = make_float4(0.f, 0.f, 0.f, 0.f);
        if (bm + lr < M && k0 + lc < K)
            a4 = *(const float4*)(A + (size_t)(bm + lr) * K + k0 + lc);
        if (bn + lr < N && k0 + lc < K)
            b4 = *(const float4*)(Bm + (size_t)(bn + lr) * K + k0 + lc);
        __syncthreads();
        As[lc + 0][lr] = a4.x; As[lc + 1][lr] = a4.y;
        As[lc + 2][lr] = a4.z; As[lc + 3][lr] = a4.w;
        Bs[lc + 0][lr] = b4.x; Bs[lc + 1][lr] = b4.y;
        Bs[lc + 2][lr] = b4.z; Bs[lc + 3][lr] = b4.w;
        __syncthreads();
#pragma unroll
        for (int kk = 0; kk < 8; kk++) {
            float ar[8], br[8];
            *(float4*)(ar)     = *(const float4*)(&As[kk][tr]);
            *(float4*)(ar + 4) = *(const float4*)(&As[kk][tr + 4]);
            *(float4*)(br)     = *(const float4*)(&Bs[kk][tc]);
            *(float4*)(br + 4) = *(const float4*)(&Bs[kk][tc + 4]);
#pragma unroll
            for (int i = 0; i < 8; i++)
#pragma unroll
                for (int j = 0; j < 8; j++) acc[i][j] += ar[i] * br[j];
        }
    }
#pragma unroll
    for (int i = 0; i < 8; i++) {
        int row = bm + tr + i;
        if (row >= M) continue;
#pragma unroll
        for (int j = 0; j < 8; j++) {
            int col = bn + tc + j;
            if (col >= N) continue;
            float v = acc[i][j];
            if (bias1) v += bias1[col];
            if (bias2) v += bias2[col];
            if (relu) v = fmaxf(v, 0.f);
            C[(size_t)row * N + col] = v;
        }
    }
}

// ---------------- gate transpose: gates[d][b*T+t][1024] -> gt[d][t][g][b] ----------------
// grid (8 g-chunks, T, 2 dirs), 256 threads, smem tiled, coalesced both sides.
__global__ void __launch_bounds__(256) tgates_kernel(
    const float* __restrict__ gates, float* __restrict__ gt, int T)
{
    __shared__ float sm[128][33];
    const int tid = threadIdx.x;
    const int gc = blockIdx.x;      // 0..7 (128 g each)
    const int t  = blockIdx.y;
    const int d  = blockIdx.z;
    const size_t ROWS = (size_t)32 * T;
#pragma unroll
    for (int pass = 0; pass < 16; pass++) {
        int b = pass * 2 + (tid >> 7);
        int g = tid & 127;
        sm[g][b] = gates[((size_t)d * ROWS + (size_t)b * T + t) * 1024 + gc * 128 + g];
    }
    __syncthreads();
    const size_t obase = (((size_t)(d * T + t)) * 1024 + gc * 128) * 32;
#pragma unroll
    for (int pass = 0; pass < 16; pass++) {
        int g = pass * 8 + (tid >> 5);
        int b = tid & 31;
        gt[obase + (size_t)g * 32 + b] = sm[g][b];
    }
}

// ---------------- persistent biLSTM recurrence (v2) ----------------
// 64 blocks (32 unit-slices x 2 dirs), 256 threads. gt layout [d][t][g][b]:
// gate loads are 1 line/warp and software-pipelined one step ahead.
// hbuf layout [buf][d][u][b] -> coalesced staging loads and hnext stores.
__global__ void reset_bar() { g_barcnt2[0] = 0u; g_barcnt2[1] = 0u; }

__global__ void __launch_bounds__(256) lstm_persist(
    const float* __restrict__ gt, const float* __restrict__ whh,
    float* __restrict__ hbuf, float* __restrict__ rep, int T)
{
    __shared__ float sh[256 * 33];   // h_prev (this dir), k-major, padded
    const int tid = threadIdx.x;
    const int d    = blockIdx.x >> 5;
    const int ublk = blockIdx.x & 31;
    const int u  = (ublk << 3) + (tid >> 5);  // hidden unit (fixed per warp)
    const int bb = tid & 31;                  // batch (lane)
    const int h_idx = (d * 256 + u) * 32 + bb;

    const float4* w0 = (const float4*)(whh + ((size_t)d * 1024 +        u) * 256);
    const float4* w1 = (const float4*)(whh + ((size_t)d * 1024 + 256  + u) * 256);
    const float4* w2 = (const float4*)(whh + ((size_t)d * 1024 + 512  + u) * 256);
    const float4* w3 = (const float4*)(whh + ((size_t)d * 1024 + 768  + u) * 256);

    // gt address for (t): (((d*T + t)*1024) + gate*256 + u)*32 + bb
    const size_t gtd = (size_t)d * T;
    float cc = 0.f;

    // preload gates for step 0
    int t0 = (d == 0) ? 0 : (T - 1);
    size_t gb = ((gtd + t0) * 1024 + u) * 32 + bb;
    float cgi = gt[gb];
    float cgf = gt[gb + 256 * 32];
    float cgg = gt[gb + 512 * 32];
    float cgo = gt[gb + 768 * 32];

    for (int s = 0; s < T; s++) {
        const float* hprev = hbuf + (size_t)(s & 1) * 16384;
        float* hnext       = hbuf + (size_t)((s & 1) ^ 1) * 16384;

        // stage h_prev into smem (k-major, padded): coalesced gmem reads
        if (s == 0) {
            for (int idx = tid; idx < 32 * 256; idx += 256) {
                int b = idx & 31, k = idx >> 5;
                sh[k * 33 + b] = 0.f;
            }
        } else {
            for (int idx = tid; idx < 32 * 256; idx += 256) {
                int b = idx & 31, k = idx >> 5;
                sh[k * 33 + b] = hprev[(d * 256 + k) * 32 + b];
            }
        }

        // prefetch next step's gates (independent of h -> hides DRAM latency)
        float ngi = 0.f, ngf = 0.f, ngg = 0.f, ngo = 0.f;
        if (s + 1 < T) {
            int tn = (d == 0) ? (s + 1) : (T - 2 - s);
            size_t gn = ((gtd + tn) * 1024 + u) * 32 + bb;
            ngi = gt[gn];
            ngf = gt[gn + 256 * 32];
            ngg = gt[gn + 512 * 32];
            ngo = gt[gn + 768 * 32];
        }
        __syncthreads();

        float a0 = 0.f, a1 = 0.f, a2 = 0.f, a3 = 0.f;
#pragma unroll 4
        for (int k4 = 0; k4 < 64; k4++) {
            float4 wa = w0[k4], wb = w1[k4], wc = w2[k4], wd = w3[k4];
            const float* hp = &sh[(k4 << 2) * 33 + bb];
            float h0 = hp[0], h1 = hp[33], h2 = hp[66], h3 = hp[99];
            a0 += wa.x * h0 + wa.y * h1 + wa.z * h2 + wa.w * h3;
            a1 += wb.x * h0 + wb.y * h1 + wb.z * h2 + wb.w * h3;
            a2 += wc.x * h0 + wc.y * h1 + wc.z * h2 + wc.w * h3;
            a3 += wd.x * h0 + wd.y * h1 + wd.z * h2 + wd.w * h3;
        }

        const int t = (d == 0) ? s : (T - 1 - s);
        float ig = sigmoidf_(cgi + a0);
        float fg = sigmoidf_(cgf + a1);
        float gg = tanhf(cgg + a2);
        float og = sigmoidf_(cgo + a3);
        float cn = fg * cc + ig * gg;
        cc = cn;
        float hn = og * tanhf(cn);
        hnext[h_idx] = hn;                                   // coalesced
        rep[((size_t)bb * T + t) * 512 + (d << 8) + u] = hn; // scattered, fire&forget

        cgi = ngi; cgf = ngf; cgg = ngg; cgo = ngo;

        // ---- per-direction grid barrier (release-red / acquire-ld spin) ----
        __syncthreads();
        if (tid == 0) {
            unsigned* ctr = &g_barcnt2[d];
            asm volatile("red.release.gpu.global.add.u32 [%0], 1;" :: "l"(ctr) : "memory");
            unsigned target = 32u * (unsigned)(s + 1), v;
            do {
                asm volatile("ld.acquire.gpu.global.u32 %0, [%1];" : "=r"(v) : "l"(ctr) : "memory");
            } while (v < target);
        }
        __syncthreads();
    }
}

// ---------------- attention: uw2[r] = dot(U[r], w2) ----------------
__global__ void __launch_bounds__(256) uw2_kernel(
    const float* __restrict__ U, const float* __restrict__ attw, float* __restrict__ uw2)
{
    int w = threadIdx.x >> 5, lane = threadIdx.x & 31;
    int row = blockIdx.x * 8 + w;
    const float* w2 = attw + 512;
    float acc = 0.f;
    const float* u = U + (size_t)row * 512;
    for (int i = lane; i < 512; i += 32) acc += u[i] * w2[i];
#pragma unroll
    for (int o = 16; o; o >>= 1) acc += __shfl_xor_sync(0xffffffffu, acc, o);
    if (lane == 0) uw2[row] = acc;
}

// ---------------- attention main ----------------
__global__ void __launch_bounds__(256) attn_s(
    const float* __restrict__ Hc, const float* __restrict__ U,
    const float* __restrict__ attw, const float* __restrict__ attb,
    const float* __restrict__ uw2, float* __restrict__ G, float* __restrict__ Smax)
{
    __shared__ float hc[512], hw3[512], sS[64], wsum[8];
    __shared__ float sHw1, sMx, sSum;
    const int row = blockIdx.x;
    const int b = row >> 9;
    const int tid = threadIdx.x;
    const float* w1 = attw;
    const float* w3 = attw + 1024;
    float p0 = 0.f;
    for (int i = tid; i < 512; i += 256) {
        float v = Hc[(size_t)row * 512 + i];
        hc[i] = v; hw3[i] = v * w3[i];
        p0 += v * w1[i];
    }
#pragma unroll
    for (int o = 16; o; o >>= 1) p0 += __shfl_xor_sync(0xffffffffu, p0, o);
    int w = tid >> 5, lane = tid & 31;
    if (lane == 0) wsum[w] = p0;
    __syncthreads();
    if (tid == 0) {
        float s = 0.f;
        for (int i = 0; i < 8; i++) s += wsum[i];
        sHw1 = s;
    }
    __syncthreads();
    float bval = attb[0];
    for (int jj = 0; jj < 8; jj++) {
        int j = w * 8 + jj;
        const float* u = U + ((size_t)(b * 64 + j)) * 512;
        float acc = 0.f;
        for (int k = lane; k < 512; k += 32) acc += hw3[k] * u[k];
#pragma unroll
        for (int o = 16; o; o >>= 1) acc += __shfl_xor_sync(0xffffffffu, acc, o);
        if (lane == 0) sS[j] = sHw1 + uw2[b * 64 + j] + acc + bval;
    }
    __syncthreads();
    if (tid == 0) {
        float mx = -1e30f;
        for (int j = 0; j < 64; j++) mx = fmaxf(mx, sS[j]);
        float sm = 0.f;
        for (int j = 0; j < 64; j++) sm += expf(sS[j] - mx);
        sMx = mx; sSum = sm;
        Smax[row] = mx;
    }
    __syncthreads();
    if (tid < 64) sS[tid] = expf(sS[tid] - sMx) / sSum;
    __syncthreads();
    for (int half = 0; half < 2; half++) {
        int dc = tid + half * 256;
        float acc = 0.f;
        for (int j = 0; j < 64; j++)
            acc += sS[j] * U[((size_t)(b * 64 + j)) * 512 + dc];
        float hv = hc[dc];
        G[(size_t)row * 2048 + dc]        = hv;
        G[(size_t)row * 2048 + 512  + dc] = acc;
        G[(size_t)row * 2048 + 1024 + dc] = hv * acc;
    }
}

// ---------------- q2c ----------------
__global__ void __launch_bounds__(256) attn_q2c(
    const float* __restrict__ Smax, const float* __restrict__ Hc, float* __restrict__ q2c)
{
    __shared__ float p[512];
    __shared__ float sMx, sSum;
    const int b = blockIdx.x, tid = threadIdx.x;
    for (int i = tid; i < 512; i += 256) p[i] = Smax[b * 512 + i];
    __syncthreads();
    if (tid == 0) {
        float mx = -1e30f;
        for (int t = 0; t < 512; t++) mx = fmaxf(mx, p[t]);
        float sm = 0.f;
        for (int t = 0; t < 512; t++) sm += expf(p[t] - mx);
        sMx = mx; sSum = sm;
    }
    __syncthreads();
    for (int i = tid; i < 512; i += 256) p[i] = expf(p[i] - sMx) / sSum;
    __syncthreads();
    for (int half = 0; half < 2; half++) {
        int dc = tid + half * 256;
        float acc = 0.f;
        for (int t = 0; t < 512; t++)
            acc += p[t] * Hc[((size_t)(b * 512 + t)) * 512 + dc];
        q2c[b * 512 + dc] = acc;
    }
}

// ---------------- G[:,1536:2048] = Hc * q2c[b] ----------------
__global__ void __launch_bounds__(256) g4_kernel(
    const float* __restrict__ Hc, const float* __restrict__ q2c, float* __restrict__ G)
{
    int idx = blockIdx.x * 256 + threadIdx.x;
    if (idx >= (int)(NCs * 512)) return;
    int row = idx >> 9, dc = idx & 511;
    int b = row >> 9;
    G[(size_t)row * 2048 + 1536 + dc] = Hc[idx] * q2c[(b << 9) + dc];
}

// ---------------- final logits ----------------
__global__ void __launch_bounds__(256) final_dot(
    const float* __restrict__ G, const float* __restrict__ M,
    const float* __restrict__ pw, const float* __restrict__ pb,
    float* __restrict__ out)
{
    int w = threadIdx.x >> 5, lane = threadIdx.x & 31;
    int row = blockIdx.x * 8 + w;
    float acc = 0.f;
    const float* g = G + (size_t)row * 2048;
    for (int i = lane; i < 2048; i += 32) acc += g[i] * pw[i];
    const float* m = M + (size_t)row * 512;
    for (int i = lane; i < 512; i += 32) acc += m[i] * pw[2048 + i];
#pragma unroll
    for (int o = 16; o; o >>= 1) acc += __shfl_xor_sync(0xffffffffu, acc, o);
    if (lane == 0) out[row] = acc + pb[0];
}

// ---------------- host orchestration ----------------
static inline void launch_sgemm(const float* A, const float* Bm, float* C,
                                const float* b1, const float* b2,
                                int M, int N, int K, int relu)
{
    dim3 grid((N + 127) / 128, (M + 127) / 128);
    sgemm_tn<<<grid, 256>>>(A, Bm, C, b1, b2, M, N, K, relu);
}

extern "C" void kernel_launch(void* const* d_in, const int* in_sizes, int n_in,
                              void* d_out, int out_size)
{
    (void)in_sizes; (void)n_in; (void)out_size;
    const int*   qtok      = (const int*)d_in[0];
    const int*   ctok      = (const int*)d_in[1];
    const float* emb       = (const float*)d_in[2];
    const float* hw_lin_w  = (const float*)d_in[3];
    const float* hw_lin_b  = (const float*)d_in[4];
    const float* hw_gate_w = (const float*)d_in[5];
    const float* hw_gate_b = (const float*)d_in[6];
    const float* ctx_wih   = (const float*)d_in[7];
    const float* ctx_whh   = (const float*)d_in[8];
    const float* ctx_bih   = (const float*)d_in[9];
    const float* ctx_bhh   = (const float*)d_in[10];
    const float* mod1_wih  = (const float*)d_in[11];
    const float* mod1_whh  = (const float*)d_in[12];
    const float* mod1_bih  = (const float*)d_in[13];
    const float* mod1_bhh  = (const float*)d_in[14];
    const float* mod2_wih  = (const float*)d_in[15];
    const float* mod2_whh  = (const float*)d_in[16];
    const float* mod2_bih  = (const float*)d_in[17];
    const float* mod2_bhh  = (const float*)d_in[18];
    const float* dec_wih   = (const float*)d_in[19];
    const float* dec_whh   = (const float*)d_in[20];
    const float* dec_bih   = (const float*)d_in[21];
    const float* dec_bhh   = (const float*)d_in[22];
    const float* att_w     = (const float*)d_in[23];
    const float* att_b     = (const float*)d_in[24];
    const float* p1_w      = (const float*)d_in[25];
    const float* p1_b      = (const float*)d_in[26];
    const float* p2_w      = (const float*)d_in[27];
    const float* p2_b      = (const float*)d_in[28];
    float* out = (float*)d_out;

    float* S = nullptr;
    cudaGetSymbolAddress((void**)&S, g_scratch);
    float* cx    = S + OFF_CX;
    float* qx    = S + OFF_QX;
    float* hb    = S + OFF_HB;
    float* tb    = S + OFF_TB;
    float* crep  = S + OFF_CREP;
    float* qrep  = S + OFF_QREP;
    float* Gb    = S + OFF_G;
    float* Ma    = S + OFF_MA;
    float* Mb    = S + OFF_MB;
    float* M2b   = S + OFF_M2;
    float* gates = S + OFF_GATES;
    float* gtb   = S + OFF_GT;
    float* Hbuf  = S + OFF_H;
    float* smax  = S + OFF_SMAX;
    float* uw2b  = S + OFF_UW2;
    float* q2cb  = S + OFF_Q2C;

    const int NC = (int)NCs;
    const int NQ = (int)NQs;

    // 1. embedding gather
    gather_embed<<<(NC * E_ + 255) / 256, 256>>>(ctok, emb, cx, NC);
    gather_embed<<<(NQ * E_ + 255) / 256, 256>>>(qtok, emb, qx, NQ);

    // 2. highway (2 layers), context then question
    for (int l = 0; l < 2; l++) {
        launch_sgemm(cx, hw_lin_w + (size_t)l * E_ * E_, hb, hw_lin_b + l * E_, nullptr, NC, E_, E_, 1);
        launch_sgemm(cx, hw_gate_w + (size_t)l * E_ * E_, tb, hw_gate_b + l * E_, nullptr, NC, E_, E_, 1);
        hw_combine<<<(NC * E_ + 255) / 256, 256>>>(cx, hb, tb, NC * E_);
    }
    for (int l = 0; l < 2; l++) {
        launch_sgemm(qx, hw_lin_w + (size_t)l * E_ * E_, hb, hw_lin_b + l * E_, nullptr, NQ, E_, E_, 1);
        launch_sgemm(qx, hw_gate_w + (size_t)l * E_ * E_, tb, hw_gate_b + l * E_, nullptr, NQ, E_, E_, 1);
        hw_combine<<<(NQ * E_ + 255) / 256, 256>>>(qx, hb, tb, NQ * E_);
    }

    // one biLSTM = 2 gate GEMMs + transpose + 1 persistent recurrence kernel
    #define RUN_BILSTM(Xin, WIH, WHH, BIH, BHH, KDIM, ROWS, TLEN, REP)                         \
        do {                                                                                   \
            for (int d = 0; d < 2; d++)                                                        \
                launch_sgemm((Xin), (WIH) + (size_t)d * 1024 * (KDIM),                         \
                             gates + (size_t)d * (ROWS) * 1024,                                \
                             (BIH) + d * 1024, (BHH) + d * 1024, (ROWS), 1024, (KDIM), 0);     \
            tgates_kernel<<<dim3(8, (TLEN), 2), 256>>>(gates, gtb, (TLEN));                    \
            reset_bar<<<1, 1>>>();                                                             \
            lstm_persist<<<64, 256>>>(gtb, (WHH), Hbuf, (REP), (TLEN));                        \
        } while (0)

    // 3. contextual biLSTM
    RUN_BILSTM(cx, ctx_wih, ctx_whh, ctx_bih, ctx_bhh, E_, NC, T_, crep);
    RUN_BILSTM(qx, ctx_wih, ctx_whh, ctx_bih, ctx_bhh, E_, NQ, J_, qrep);

    // 4. attention -> G
    uw2_kernel<<<NQ / 8, 256>>>(qrep, att_w, uw2b);
    attn_s<<<NC, 256>>>(crep, qrep, att_w, att_b, uw2b, Gb, smax);
    attn_q2c<<<B_, 256>>>(smax, crep, q2cb);
    g4_kernel<<<(NC * 512 + 255) / 256, 256>>>(crep, q2cb, Gb);

    // 5. modeling biLSTMs
    RUN_BILSTM(Gb, mod1_wih, mod1_whh, mod1_bih, mod1_bhh, 2048, NC, T_, Ma);
    RUN_BILSTM(Ma, mod2_wih, mod2_whh, mod2_bih, mod2_bhh, 512, NC, T_, Mb);

    // 6. start logits
    final_dot<<<NC / 8, 256>>>(Gb, Mb, p1_w, p1_b, out);

    // 7. decode biLSTM + end logits
    RUN_BILSTM(Mb, dec_wih, dec_whh, dec_bih, dec_bhh, 512, NC, T_, M2b);
    final_dot<<<NC / 8, 256>>>(Gb, M2b, p2_w, p2_b, out + NC);

    #undef RUN_BILSTM
}

// round 11
// speedup vs baseline: 1.7577x; 1.6609x over previous
#include <cuda_runtime.h>
#include <math.h>

// ---------------- problem constants ----------------
#define B_ 32
#define T_ 512
#define J_ 64
#define E_ 300
#define H_ 256

static constexpr size_t NCs = 16384;  // B*T
static constexpr size_t NQs = 2048;   // B*J

// ---------------- scratch layout (single __device__ arena) ----------------
static constexpr size_t OFF_CX    = 0;                          // [NC][300]
static constexpr size_t OFF_QX    = OFF_CX   + NCs * 300;       // [NQ][300]
static constexpr size_t OFF_HB    = OFF_QX   + NQs * 300;       // [NC][300]
static constexpr size_t OFF_TB    = OFF_HB   + NCs * 300;       // [NC][300]
static constexpr size_t OFF_CREP  = OFF_TB   + NCs * 300;       // [NC][512]
static constexpr size_t OFF_QREP  = OFF_CREP + NCs * 512;       // [NQ][512]
static constexpr size_t OFF_G     = OFF_QREP + NQs * 512;       // [NC][2048]
static constexpr size_t OFF_MA    = OFF_G    + NCs * 2048;      // [NC][512]
static constexpr size_t OFF_MB    = OFF_MA   + NCs * 512;       // [NC][512]
static constexpr size_t OFF_M2    = OFF_MB   + NCs * 512;       // [NC][512]
static constexpr size_t OFF_GATES = OFF_M2   + NCs * 512;       // [2][NC][1024] (GEMM out)
static constexpr size_t OFF_GT    = OFF_GATES + 2 * NCs * 1024; // [2][T][1024][32] transposed
static constexpr size_t OFF_H     = OFF_GT   + 2 * NCs * 1024;  // 2 x [2][256][32]
static constexpr size_t OFF_SMAX  = OFF_H    + 2 * 16384;       // [NC]
static constexpr size_t OFF_UW2   = OFF_SMAX + 16384;           // [NQ]
static constexpr size_t OFF_Q2C   = OFF_UW2  + 2048;            // [B][512]
static constexpr size_t SCRATCH_TOTAL = OFF_Q2C + 32 * 512;

__device__ float g_scratch[SCRATCH_TOTAL];
__device__ unsigned g_barcnt2[2];

__device__ __forceinline__ float sigmoidf_(float x) { return 1.f / (1.f + expf(-x)); }

// ---------------- embedding gather ----------------
__global__ void __launch_bounds__(256) gather_embed(
    const int* __restrict__ tok, const float* __restrict__ emb,
    float* __restrict__ out, int nrows)
{
    int idx = blockIdx.x * 256 + threadIdx.x;
    int total = nrows * E_;
    if (idx >= total) return;
    int r = idx / E_;
    int e = idx - r * E_;
    out[idx] = emb[(size_t)tok[r] * E_ + e];
}

// ---------------- highway combine ----------------
__global__ void __launch_bounds__(256) hw_combine(
    float* __restrict__ x, const float* __restrict__ h,
    const float* __restrict__ t, int n)
{
    int i = blockIdx.x * 256 + threadIdx.x;
    if (i < n) { float tv = t[i]; x[i] = h[i] * tv + (1.f - tv) * x[i]; }
}

// ---------------- SGEMM: C[M,N] = A[M,K] @ B[N,K]^T (+bias1+bias2, opt relu) ------------
// software-pipelined: store tile -> sync -> prefetch next tile -> compute -> sync
__global__ void __launch_bounds__(256) sgemm_tn(
    const float* __restrict__ A, const float* __restrict__ Bm,
    float* __restrict__ C,
    const float* __restrict__ bias1, const float* __restrict__ bias2,
    int M, int N, int K, int relu)
{
    __shared__ float As[8][132];
    __shared__ float Bs[8][132];
    const int tid = threadIdx.x;
    const int bm = blockIdx.y * 128, bn = blockIdx.x * 128;
    const int lr = tid >> 1;
    const int lc = (tid & 1) << 2;
    const int tr = (tid >> 4) << 3;
    const int tc = (tid & 15) << 3;
    float acc[8][8];
#pragma unroll
    for (int i = 0; i < 8; i++)
#pragma unroll
        for (int j = 0; j < 8; j++) acc[i][j] = 0.f;

    // prologue: load first tile
    float4 a4 = make_float4(0.f, 0.f, 0.f, 0.f);
    float4 b4 = make_float4(0.f, 0.f, 0.f, 0.f);
    if (bm + lr < M && lc < K)
        a4 = *(const float4*)(A + (size_t)(bm + lr) * K + lc);
    if (bn + lr < N && lc < K)
        b4 = *(const float4*)(Bm + (size_t)(bn + lr) * K + lc);

    for (int k0 = 0; k0 < K; k0 += 8) {
        As[lc + 0][lr] = a4.x; As[lc + 1][lr] = a4.y;
        As[lc + 2][lr] = a4.z; As[lc + 3][lr] = a4.w;
        Bs[lc + 0][lr] = b4.x; Bs[lc + 1][lr] = b4.y;
        Bs[lc + 2][lr] = b4.z; Bs[lc + 3][lr] = b4.w;
        __syncthreads();

        // prefetch next tile while computing this one
        int kn = k0 + 8;
        a4 = make_float4(0.f, 0.f, 0.f, 0.f);
        b4 = make_float4(0.f, 0.f, 0.f, 0.f);
        if (kn < K) {
            if (bm + lr < M && kn + lc < K)
                a4 = *(const float4*)(A + (size_t)(bm + lr) * K + kn + lc);
            if (bn + lr < N && kn + lc < K)
                b4 = *(const float4*)(Bm + (size_t)(bn + lr) * K + kn + lc);
        }

#pragma unroll
        for (int kk = 0; kk < 8; kk++) {
            float ar[8], br[8];
            *(float4*)(ar)     = *(const float4*)(&As[kk][tr]);
            *(float4*)(ar + 4) = *(const float4*)(&As[kk][tr + 4]);
            *(float4*)(br)     = *(const float4*)(&Bs[kk][tc]);
            *(float4*)(br + 4) = *(const float4*)(&Bs[kk][tc + 4]);
#pragma unroll
            for (int i = 0; i < 8; i++)
#pragma unroll
                for (int j = 0; j < 8; j++) acc[i][j] += ar[i] * br[j];
        }
        __syncthreads();
    }
#pragma unroll
    for (int i = 0; i < 8; i++) {
        int row = bm + tr + i;
        if (row >= M) continue;
#pragma unroll
        for (int j = 0; j < 8; j++) {
            int col = bn + tc + j;
            if (col >= N) continue;
            float v = acc[i][j];
            if (bias1) v += bias1[col];
            if (bias2) v += bias2[col];
            if (relu) v = fmaxf(v, 0.f);
            C[(size_t)row * N + col] = v;
        }
    }
}

// ---------------- gate transpose: gates[d][b*T+t][1024] -> gt[d][t][g][b] ----------------
__global__ void __launch_bounds__(256) tgates_kernel(
    const float* __restrict__ gates, float* __restrict__ gt, int T)
{
    __shared__ float sm[128][33];
    const int tid = threadIdx.x;
    const int gc = blockIdx.x;      // 0..7 (128 g each)
    const int t  = blockIdx.y;
    const int d  = blockIdx.z;
    const size_t ROWS = (size_t)32 * T;
#pragma unroll
    for (int pass = 0; pass < 16; pass++) {
        int b = pass * 2 + (tid >> 7);
        int g = tid & 127;
        sm[g][b] = gates[((size_t)d * ROWS + (size_t)b * T + t) * 1024 + gc * 128 + g];
    }
    __syncthreads();
    const size_t obase = (((size_t)(d * T + t)) * 1024 + gc * 128) * 32;
#pragma unroll
    for (int pass = 0; pass < 16; pass++) {
        int g = pass * 8 + (tid >> 5);
        int b = tid & 31;
        gt[obase + (size_t)g * 32 + b] = sm[g][b];
    }
}

// ---------------- persistent biLSTM recurrence (v3) ----------------
// 128 blocks (64 unit-quads x 2 dirs), 256 threads = 8 warps.
// warp w: unit ui = w>>1 (of block's 4), gate-pair gp = w&1 ({i,f} or {g,o}),
// lanes = batch. Weights live in SMEM (loaded once). Per-thread: 2 gate rows.
// Gate pre-activations exchanged through smem; gp==0 warps do the pointwise.
__global__ void reset_bar() { g_barcnt2[0] = 0u; g_barcnt2[1] = 0u; }

__global__ void __launch_bounds__(256) lstm_persist(
    const float* __restrict__ gt, const float* __restrict__ whh,
    float* __restrict__ hbuf, float* __restrict__ rep, int T)
{
    __shared__ float sh[256 * 33];      // h_prev (this dir), k-major, padded
    __shared__ float wsm[16 * 256];     // this block's 16 weight rows
    __shared__ float exch[4][4][32];    // [unit][gate][batch] pre-activations

    const int tid  = threadIdx.x;
    const int d    = blockIdx.x >> 6;           // direction
    const int ublk = blockIdx.x & 63;           // unit-quad index
    const int w    = tid >> 5;
    const int lane = tid & 31;
    const int ui   = w >> 1;                    // 0..3 (unit within block)
    const int gp   = w & 1;                     // gate pair: 0 -> {0,1}, 1 -> {2,3}
    const int ug   = (ublk << 2) + ui;          // global hidden unit
    const int bb   = lane;                      // batch

    // load this warp's 2 weight rows into smem (once)
    for (int g = 0; g < 2; g++) {
        int gate = gp * 2 + g;
        const float4* src = (const float4*)(whh + ((size_t)d * 1024 + gate * 256 + ug) * 256);
        float4* dst = (float4*)(wsm + (ui * 4 + gate) * 256);
        for (int i = lane; i < 64; i += 32) dst[i] = src[i];
    }

    const float4* wp0 = (const float4*)(wsm + (ui * 4 + gp * 2) * 256);
    const float4* wp1 = wp0 + 64;

    const size_t gtd = (size_t)d * T;
    float cc = 0.f;                              // cell state (gp==0 warps)

    // preload gates for step 0 (this warp's 2 gates)
    int t0 = (d == 0) ? 0 : (T - 1);
    size_t gb0 = ((gtd + t0) * 1024 + (size_t)(gp * 2) * 256 + ug) * 32 + bb;
    float cg0 = gt[gb0];
    float cg1 = gt[gb0 + 256 * 32];

    for (int s = 0; s < T; s++) {
        const float* hprev = hbuf + (size_t)(s & 1) * 16384;
        float* hnext       = hbuf + (size_t)((s & 1) ^ 1) * 16384;

        // stage h_prev into smem (k-major, padded)
        if (s == 0) {
            for (int idx = tid; idx < 32 * 256; idx += 256) {
                int b = idx & 31, k = idx >> 5;
                sh[k * 33 + b] = 0.f;
            }
        } else {
            for (int idx = tid; idx < 32 * 256; idx += 256) {
                int b = idx & 31, k = idx >> 5;
                sh[k * 33 + b] = hprev[(d * 256 + k) * 32 + b];
            }
        }

        // prefetch next step's gates (independent of h)
        float ng0 = 0.f, ng1 = 0.f;
        if (s + 1 < T) {
            int tn = (d == 0) ? (s + 1) : (T - 2 - s);
            size_t gn = ((gtd + tn) * 1024 + (size_t)(gp * 2) * 256 + ug) * 32 + bb;
            ng0 = gt[gn];
            ng1 = gt[gn + 256 * 32];
        }
        __syncthreads();

        // 2 gate rows x 256 MACs, weights from smem (uniform broadcast)
        float a0 = 0.f, a1 = 0.f;
#pragma unroll 8
        for (int k4 = 0; k4 < 64; k4++) {
            float4 wa = wp0[k4], wb = wp1[k4];
            const float* hp = &sh[(k4 << 2) * 33 + bb];
            float h0 = hp[0], h1 = hp[33], h2 = hp[66], h3 = hp[99];
            a0 += wa.x * h0 + wa.y * h1 + wa.z * h2 + wa.w * h3;
            a1 += wb.x * h0 + wb.y * h1 + wb.z * h2 + wb.w * h3;
        }
        exch[ui][gp * 2 + 0][bb] = a0 + cg0;
        exch[ui][gp * 2 + 1][bb] = a1 + cg1;
        cg0 = ng0; cg1 = ng1;
        __syncthreads();

        // pointwise + state update on gp==0 warps
        if (gp == 0) {
            float xi = exch[ui][0][bb];
            float xf = exch[ui][1][bb];
            float xg = exch[ui][2][bb];
            float xo = exch[ui][3][bb];
            float ig = sigmoidf_(xi), fg = sigmoidf_(xf), og = sigmoidf_(xo);
            float gg = tanhf(xg);
            float cn = fg * cc + ig * gg;
            cc = cn;
            float hn = og * tanhf(cn);
            const int t = (d == 0) ? s : (T - 1 - s);
            hnext[(d * 256 + ug) * 32 + bb] = hn;               // coalesced
            rep[((size_t)bb * T + t) * 512 + (d << 8) + ug] = hn;
        }

        // ---- per-direction grid barrier ----
        __syncthreads();
        if (tid == 0) {
            unsigned* ctr = &g_barcnt2[d];
            asm volatile("red.release.gpu.global.add.u32 [%0], 1;" :: "l"(ctr) : "memory");
            unsigned target = 64u * (unsigned)(s + 1), v;
            do {
                asm volatile("ld.acquire.gpu.global.u32 %0, [%1];" : "=r"(v) : "l"(ctr) : "memory");
            } while (v < target);
        }
        __syncthreads();
    }
}

// ---------------- attention: uw2[r] = dot(U[r], w2) ----------------
__global__ void __launch_bounds__(256) uw2_kernel(
    const float* __restrict__ U, const float* __restrict__ attw, float* __restrict__ uw2)
{
    int w = threadIdx.x >> 5, lane = threadIdx.x & 31;
    int row = blockIdx.x * 8 + w;
    const float* w2 = attw + 512;
    float acc = 0.f;
    const float* u = U + (size_t)row * 512;
    for (int i = lane; i < 512; i += 32) acc += u[i] * w2[i];
#pragma unroll
    for (int o = 16; o; o >>= 1) acc += __shfl_xor_sync(0xffffffffu, acc, o);
    if (lane == 0) uw2[row] = acc;
}

// ---------------- attention main ----------------
__global__ void __launch_bounds__(256) attn_s(
    const float* __restrict__ Hc, const float* __restrict__ U,
    const float* __restrict__ attw, const float* __restrict__ attb,
    const float* __restrict__ uw2, float* __restrict__ G, float* __restrict__ Smax)
{
    __shared__ float hc[512], hw3[512], sS[64], wsum[8];
    __shared__ float sHw1, sMx, sSum;
    const int row = blockIdx.x;
    const int b = row >> 9;
    const int tid = threadIdx.x;
    const float* w1 = attw;
    const float* w3 = attw + 1024;
    float p0 = 0.f;
    for (int i = tid; i < 512; i += 256) {
        float v = Hc[(size_t)row * 512 + i];
        hc[i] = v; hw3[i] = v * w3[i];
        p0 += v * w1[i];
    }
#pragma unroll
    for (int o = 16; o; o >>= 1) p0 += __shfl_xor_sync(0xffffffffu, p0, o);
    int w = tid >> 5, lane = tid & 31;
    if (lane == 0) wsum[w] = p0;
    __syncthreads();
    if (tid == 0) {
        float s = 0.f;
        for (int i = 0; i < 8; i++) s += wsum[i];
        sHw1 = s;
    }
    __syncthreads();
    float bval = attb[0];
    for (int jj = 0; jj < 8; jj++) {
        int j = w * 8 + jj;
        const float* u = U + ((size_t)(b * 64 + j)) * 512;
        float acc = 0.f;
        for (int k = lane; k < 512; k += 32) acc += hw3[k] * u[k];
#pragma unroll
        for (int o = 16; o; o >>= 1) acc += __shfl_xor_sync(0xffffffffu, acc, o);
        if (lane == 0) sS[j] = sHw1 + uw2[b * 64 + j] + acc + bval;
    }
    __syncthreads();
    if (tid == 0) {
        float mx = -1e30f;
        for (int j = 0; j < 64; j++) mx = fmaxf(mx, sS[j]);
        float sm = 0.f;
        for (int j = 0; j < 64; j++) sm += expf(sS[j] - mx);
        sMx = mx; sSum = sm;
        Smax[row] = mx;
    }
    __syncthreads();
    if (tid < 64) sS[tid] = expf(sS[tid] - sMx) / sSum;
    __syncthreads();
    for (int half = 0; half < 2; half++) {
        int dc = tid + half * 256;
        float acc = 0.f;
        for (int j = 0; j < 64; j++)
            acc += sS[j] * U[((size_t)(b * 64 + j)) * 512 + dc];
        float hv = hc[dc];
        G[(size_t)row * 2048 + dc]        = hv;
        G[(size_t)row * 2048 + 512  + dc] = acc;
        G[(size_t)row * 2048 + 1024 + dc] = hv * acc;
    }
}

// ---------------- q2c ----------------
__global__ void __launch_bounds__(256) attn_q2c(
    const float* __restrict__ Smax, const float* __restrict__ Hc, float* __restrict__ q2c)
{
    __shared__ float p[512];
    __shared__ float sMx, sSum;
    const int b = blockIdx.x, tid = threadIdx.x;
    for (int i = tid; i < 512; i += 256) p[i] = Smax[b * 512 + i];
    __syncthreads();
    if (tid == 0) {
        float mx = -1e30f;
        for (int t = 0; t < 512; t++) mx = fmaxf(mx, p[t]);
        float sm = 0.f;
        for (int t = 0; t < 512; t++) sm += expf(p[t] - mx);
        sMx = mx; sSum = sm;
    }
    __syncthreads();
    for (int i = tid; i < 512; i += 256) p[i] = expf(p[i] - sMx) / sSum;
    __syncthreads();
    for (int half = 0; half < 2; half++) {
        int dc = tid + half * 256;
        float acc = 0.f;
        for (int t = 0; t < 512; t++)
            acc += p[t] * Hc[((size_t)(b * 512 + t)) * 512 + dc];
        q2c[b * 512 + dc] = acc;
    }
}

// ---------------- G[:,1536:2048] = Hc * q2c[b] ----------------
__global__ void __launch_bounds__(256) g4_kernel(
    const float* __restrict__ Hc, const float* __restrict__ q2c, float* __restrict__ G)
{
    int idx = blockIdx.x * 256 + threadIdx.x;
    if (idx >= (int)(NCs * 512)) return;
    int row = idx >> 9, dc = idx & 511;
    int b = row >> 9;
    G[(size_t)row * 2048 + 1536 + dc] = Hc[idx] * q2c[(b << 9) + dc];
}

// ---------------- final logits ----------------
__global__ void __launch_bounds__(256) final_dot(
    const float* __restrict__ G, const float* __restrict__ M,
    const float* __restrict__ pw, const float* __restrict__ pb,
    float* __restrict__ out)
{
    int w = threadIdx.x >> 5, lane = threadIdx.x & 31;
    int row = blockIdx.x * 8 + w;
    float acc = 0.f;
    const float* g = G + (size_t)row * 2048;
    for (int i = lane; i < 2048; i += 32) acc += g[i] * pw[i];
    const float* m = M + (size_t)row * 512;
    for (int i = lane; i < 512; i += 32) acc += m[i] * pw[2048 + i];
#pragma unroll
    for (int o = 16; o; o >>= 1) acc += __shfl_xor_sync(0xffffffffu, acc, o);
    if (lane == 0) out[row] = acc + pb[0];
}

// ---------------- host orchestration ----------------
static inline void launch_sgemm(const float* A, const float* Bm, float* C,
                                const float* b1, const float* b2,
                                int M, int N, int K, int relu)
{
    dim3 grid((N + 127) / 128, (M + 127) / 128);
    sgemm_tn<<<grid, 256>>>(A, Bm, C, b1, b2, M, N, K, relu);
}

extern "C" void kernel_launch(void* const* d_in, const int* in_sizes, int n_in,
                              void* d_out, int out_size)
{
    (void)in_sizes; (void)n_in; (void)out_size;
    const int*   qtok      = (const int*)d_in[0];
    const int*   ctok      = (const int*)d_in[1];
    const float* emb       = (const float*)d_in[2];
    const float* hw_lin_w  = (const float*)d_in[3];
    const float* hw_lin_b  = (const float*)d_in[4];
    const float* hw_gate_w = (const float*)d_in[5];
    const float* hw_gate_b = (const float*)d_in[6];
    const float* ctx_wih   = (const float*)d_in[7];
    const float* ctx_whh   = (const float*)d_in[8];
    const float* ctx_bih   = (const float*)d_in[9];
    const float* ctx_bhh   = (const float*)d_in[10];
    const float* mod1_wih  = (const float*)d_in[11];
    const float* mod1_whh  = (const float*)d_in[12];
    const float* mod1_bih  = (const float*)d_in[13];
    const float* mod1_bhh  = (const float*)d_in[14];
    const float* mod2_wih  = (const float*)d_in[15];
    const float* mod2_whh  = (const float*)d_in[16];
    const float* mod2_bih  = (const float*)d_in[17];
    const float* mod2_bhh  = (const float*)d_in[18];
    const float* dec_wih   = (const float*)d_in[19];
    const float* dec_whh   = (const float*)d_in[20];
    const float* dec_bih   = (const float*)d_in[21];
    const float* dec_bhh   = (const float*)d_in[22];
    const float* att_w     = (const float*)d_in[23];
    const float* att_b     = (const float*)d_in[24];
    const float* p1_w      = (const float*)d_in[25];
    const float* p1_b      = (const float*)d_in[26];
    const float* p2_w      = (const float*)d_in[27];
    const float* p2_b      = (const float*)d_in[28];
    float* out = (float*)d_out;

    float* S = nullptr;
    cudaGetSymbolAddress((void**)&S, g_scratch);
    float* cx    = S + OFF_CX;
    float* qx    = S + OFF_QX;
    float* hb    = S + OFF_HB;
    float* tb    = S + OFF_TB;
    float* crep  = S + OFF_CREP;
    float* qrep  = S + OFF_QREP;
    float* Gb    = S + OFF_G;
    float* Ma    = S + OFF_MA;
    float* Mb    = S + OFF_MB;
    float* M2b   = S + OFF_M2;
    float* gates = S + OFF_GATES;
    float* gtb   = S + OFF_GT;
    float* Hbuf  = S + OFF_H;
    float* smax  = S + OFF_SMAX;
    float* uw2b  = S + OFF_UW2;
    float* q2cb  = S + OFF_Q2C;

    const int NC = (int)NCs;
    const int NQ = (int)NQs;

    // 1. embedding gather
    gather_embed<<<(NC * E_ + 255) / 256, 256>>>(ctok, emb, cx, NC);
    gather_embed<<<(NQ * E_ + 255) / 256, 256>>>(qtok, emb, qx, NQ);

    // 2. highway (2 layers), context then question
    for (int l = 0; l < 2; l++) {
        launch_sgemm(cx, hw_lin_w + (size_t)l * E_ * E_, hb, hw_lin_b + l * E_, nullptr, NC, E_, E_, 1);
        launch_sgemm(cx, hw_gate_w + (size_t)l * E_ * E_, tb, hw_gate_b + l * E_, nullptr, NC, E_, E_, 1);
        hw_combine<<<(NC * E_ + 255) / 256, 256>>>(cx, hb, tb, NC * E_);
    }
    for (int l = 0; l < 2; l++) {
        launch_sgemm(qx, hw_lin_w + (size_t)l * E_ * E_, hb, hw_lin_b + l * E_, nullptr, NQ, E_, E_, 1);
        launch_sgemm(qx, hw_gate_w + (size_t)l * E_ * E_, tb, hw_gate_b + l * E_, nullptr, NQ, E_, E_, 1);
        hw_combine<<<(NQ * E_ + 255) / 256, 256>>>(qx, hb, tb, NQ * E_);
    }

    // one biLSTM = 2 gate GEMMs + transpose + 1 persistent recurrence kernel
    #define RUN_BILSTM(Xin, WIH, WHH, BIH, BHH, KDIM, ROWS, TLEN, REP)                         \
        do {                                                                                   \
            for (int d = 0; d < 2; d++)                                                        \
                launch_sgemm((Xin), (WIH) + (size_t)d * 1024 * (KDIM),                         \
                             gates + (size_t)d * (ROWS) * 1024,                                \
                             (BIH) + d * 1024, (BHH) + d * 1024, (ROWS), 1024, (KDIM), 0);     \
            tgates_kernel<<<dim3(8, (TLEN), 2), 256>>>(gates, gtb, (TLEN));                    \
            reset_bar<<<1, 1>>>();                                                             \
            lstm_persist<<<128, 256>>>(gtb, (WHH), Hbuf, (REP), (TLEN));                       \
        } while (0)

    // 3. contextual biLSTM
    RUN_BILSTM(cx, ctx_wih, ctx_whh, ctx_bih, ctx_bhh, E_, NC, T_, crep);
    RUN_BILSTM(qx, ctx_wih, ctx_whh, ctx_bih, ctx_bhh, E_, NQ, J_, qrep);

    // 4. attention -> G
    uw2_kernel<<<NQ / 8, 256>>>(qrep, att_w, uw2b);
    attn_s<<<NC, 256>>>(crep, qrep, att_w, att_b, uw2b, Gb, smax);
    attn_q2c<<<B_, 256>>>(smax, crep, q2cb);
    g4_kernel<<<(NC * 512 + 255) / 256, 256>>>(crep, q2cb, Gb);

    // 5. modeling biLSTMs
    RUN_BILSTM(Gb, mod1_wih, mod1_whh, mod1_bih, mod1_bhh, 2048, NC, T_, Ma);
    RUN_BILSTM(Ma, mod2_wih, mod2_whh, mod2_bih, mod2_bhh, 512, NC, T_, Mb);

    // 6. start logits
    final_dot<<<NC / 8, 256>>>(Gb, Mb, p1_w, p1_b, out);

    // 7. decode biLSTM + end logits
    RUN_BILSTM(Mb, dec_wih, dec_whh, dec_bih, dec_bhh, 512, NC, T_, M2b);
    final_dot<<<NC / 8, 256>>>(Gb, M2b, p2_w, p2_b, out + NC);

    #undef RUN_BILSTM
}

// round 12
// speedup vs baseline: 1.8328x; 1.0427x over previous
#include <cuda_runtime.h>
#include <math.h>

// ---------------- problem constants ----------------
#define B_ 32
#define T_ 512
#define J_ 64
#define E_ 300
#define H_ 256

static constexpr size_t NCs = 16384;  // B*T
static constexpr size_t NQs = 2048;   // B*J

// ---------------- scratch layout (single __device__ arena) ----------------
static constexpr size_t OFF_CX    = 0;                          // [NC][300]
static constexpr size_t OFF_QX    = OFF_CX   + NCs * 300;       // [NQ][300]
static constexpr size_t OFF_HB    = OFF_QX   + NQs * 300;       // [NC][300]
static constexpr size_t OFF_TB    = OFF_HB   + NCs * 300;       // [NC][300]
static constexpr size_t OFF_CREP  = OFF_TB   + NCs * 300;       // [NC][512]
static constexpr size_t OFF_QREP  = OFF_CREP + NCs * 512;       // [NQ][512]
static constexpr size_t OFF_G     = OFF_QREP + NQs * 512;       // [NC][2048]
static constexpr size_t OFF_MA    = OFF_G    + NCs * 2048;      // [NC][512]
static constexpr size_t OFF_MB    = OFF_MA   + NCs * 512;       // [NC][512]
static constexpr size_t OFF_M2    = OFF_MB   + NCs * 512;       // [NC][512]
static constexpr size_t OFF_GATES = OFF_M2   + NCs * 512;       // [NC][2048] (GEMM out, both dirs)
static constexpr size_t OFF_GT    = OFF_GATES + 2 * NCs * 1024; // [2][T][1024][32] transposed
static constexpr size_t OFF_H     = OFF_GT   + 2 * NCs * 1024;  // 2 x [2][256][32]
static constexpr size_t OFF_SMAX  = OFF_H    + 2 * 16384;       // [NC]
static constexpr size_t OFF_UW2   = OFF_SMAX + 16384;           // [NQ]
static constexpr size_t OFF_Q2C   = OFF_UW2  + 2048;            // [B][512]
static constexpr size_t SCRATCH_TOTAL = OFF_Q2C + 32 * 512;

__device__ float g_scratch[SCRATCH_TOTAL];
__device__ unsigned g_barcnt2[2];

__device__ __forceinline__ float sigmoidf_(float x) { return 1.f / (1.f + expf(-x)); }

__device__ __forceinline__ unsigned long long pack2_(float lo, float hi) {
    unsigned long long r;
    asm("mov.b64 %0, {%1, %2};" : "=l"(r) : "r"(__float_as_uint(lo)), "r"(__float_as_uint(hi)));
    return r;
}
#define FMA2_(d, a, b) \
    asm("fma.rn.f32x2 %0, %1, %2, %0;" : "+l"(d) : "l"(a), "l"(b))

// ---------------- embedding gather ----------------
__global__ void __launch_bounds__(256) gather_embed(
    const int* __restrict__ tok, const float* __restrict__ emb,
    float* __restrict__ out, int nrows)
{
    int idx = blockIdx.x * 256 + threadIdx.x;
    int total = nrows * E_;
    if (idx >= total) return;
    int r = idx / E_;
    int e = idx - r * E_;
    out[idx] = emb[(size_t)tok[r] * E_ + e];
}

// ---------------- highway combine ----------------
__global__ void __launch_bounds__(256) hw_combine(
    float* __restrict__ x, const float* __restrict__ h,
    const float* __restrict__ t, int n)
{
    int i = blockIdx.x * 256 + threadIdx.x;
    if (i < n) { float tv = t[i]; x[i] = h[i] * tv + (1.f - tv) * x[i]; }
}

// ---------------- SGEMM (f32x2): C[M,N] = A[M,K] @ B[N,K]^T (+bias1+bias2, opt relu) ----
// 128x128 tile, 8x(4x2) microtile with packed-pair accumulators (FFMA2),
// software-pipelined global->smem loads.
__global__ void __launch_bounds__(256, 2) sgemm_tn(
    const float* __restrict__ A, const float* __restrict__ Bm,
    float* __restrict__ C,
    const float* __restrict__ bias1, const float* __restrict__ bias2,
    int M, int N, int K, int relu)
{
    __shared__ float As[8][132];
    __shared__ float Bs[8][132];
    const int tid = threadIdx.x;
    const int bm = blockIdx.y * 128, bn = blockIdx.x * 128;
    const int lr = tid >> 1;
    const int lc = (tid & 1) << 2;
    const int tr = (tid >> 4) << 3;
    const int tc = (tid & 15) << 3;
    unsigned long long acc2[8][4];
#pragma unroll
    for (int i = 0; i < 8; i++)
#pragma unroll
        for (int j = 0; j < 4; j++) acc2[i][j] = 0ull;

    // prologue: load first tile
    float4 a4 = make_float4(0.f, 0.f, 0.f, 0.f);
    float4 b4 = make_float4(0.f, 0.f, 0.f, 0.f);
    if (bm + lr < M && lc < K)
        a4 = *(const float4*)(A + (size_t)(bm + lr) * K + lc);
    if (bn + lr < N && lc < K)
        b4 = *(const float4*)(Bm + (size_t)(bn + lr) * K + lc);

    for (int k0 = 0; k0 < K; k0 += 8) {
        As[lc + 0][lr] = a4.x; As[lc + 1][lr] = a4.y;
        As[lc + 2][lr] = a4.z; As[lc + 3][lr] = a4.w;
        Bs[lc + 0][lr] = b4.x; Bs[lc + 1][lr] = b4.y;
        Bs[lc + 2][lr] = b4.z; Bs[lc + 3][lr] = b4.w;
        __syncthreads();

        // prefetch next tile while computing this one
        int kn = k0 + 8;
        a4 = make_float4(0.f, 0.f, 0.f, 0.f);
        b4 = make_float4(0.f, 0.f, 0.f, 0.f);
        if (kn < K) {
            if (bm + lr < M && kn + lc < K)
                a4 = *(const float4*)(A + (size_t)(bm + lr) * K + kn + lc);
            if (bn + lr < N && kn + lc < K)
                b4 = *(const float4*)(Bm + (size_t)(bn + lr) * K + kn + lc);
        }

#pragma unroll
        for (int kk = 0; kk < 8; kk++) {
            float ar[8];
            *(float4*)(ar)     = *(const float4*)(&As[kk][tr]);
            *(float4*)(ar + 4) = *(const float4*)(&As[kk][tr + 4]);
            // B pairs read pre-packed straight out of smem (16B aligned)
            ulonglong2 bv0 = *(const ulonglong2*)(&Bs[kk][tc]);
            ulonglong2 bv1 = *(const ulonglong2*)(&Bs[kk][tc + 4]);
#pragma unroll
            for (int i = 0; i < 8; i++) {
                unsigned long long ad = pack2_(ar[i], ar[i]);
                FMA2_(acc2[i][0], ad, bv0.x);
                FMA2_(acc2[i][1], ad, bv0.y);
                FMA2_(acc2[i][2], ad, bv1.x);
                FMA2_(acc2[i][3], ad, bv1.y);
            }
        }
        __syncthreads();
    }
#pragma unroll
    for (int i = 0; i < 8; i++) {
        int row = bm + tr + i;
        if (row >= M) continue;
#pragma unroll
        for (int jp = 0; jp < 4; jp++) {
            float v0 = __uint_as_float((unsigned)(acc2[i][jp]));
            float v1 = __uint_as_float((unsigned)(acc2[i][jp] >> 32));
#pragma unroll
            for (int e = 0; e < 2; e++) {
                int col = bn + tc + jp * 2 + e;
                if (col >= N) continue;
                float v = e ? v1 : v0;
                if (bias1) v += bias1[col];
                if (bias2) v += bias2[col];
                if (relu) v = fmaxf(v, 0.f);
                C[(size_t)row * N + col] = v;
            }
        }
    }
}

// ---------------- gate transpose: gates[b*T+t][2048] -> gt[d][t][g][b] ----------------
__global__ void __launch_bounds__(256) tgates_kernel(
    const float* __restrict__ gates, float* __restrict__ gt, int T)
{
    __shared__ float sm[128][33];
    const int tid = threadIdx.x;
    const int gc = blockIdx.x;      // 0..7 (128 g each)
    const int t  = blockIdx.y;
    const int d  = blockIdx.z;
#pragma unroll
    for (int pass = 0; pass < 16; pass++) {
        int b = pass * 2 + (tid >> 7);
        int g = tid & 127;
        sm[g][b] = gates[((size_t)b * T + t) * 2048 + d * 1024 + gc * 128 + g];
    }
    __syncthreads();
    const size_t obase = (((size_t)(d * T + t)) * 1024 + gc * 128) * 32;
#pragma unroll
    for (int pass = 0; pass < 16; pass++) {
        int g = pass * 8 + (tid >> 5);
        int b = tid & 31;
        gt[obase + (size_t)g * 32 + b] = sm[g][b];
    }
}

// ---------------- persistent biLSTM recurrence (v4) ----------------
// 128 blocks (64 unit-quads x 2 dirs), 256 threads = 8 warps.
// sh layout [b][k] pad 260 -> h vector reads are LDS.128, conflict-free.
__global__ void reset_bar() { g_barcnt2[0] = 0u; g_barcnt2[1] = 0u; }

__global__ void __launch_bounds__(256) lstm_persist(
    const float* __restrict__ gt, const float* __restrict__ whh,
    float* __restrict__ hbuf, float* __restrict__ rep, int T)
{
    __shared__ float sh[32 * 260];      // h_prev (this dir), [b][k] padded
    __shared__ float wsm[16 * 256];     // this block's 16 weight rows
    __shared__ float exch[4][4][32];    // [unit][gate][batch] pre-activations

    const int tid  = threadIdx.x;
    const int d    = blockIdx.x >> 6;
    const int ublk = blockIdx.x & 63;
    const int w    = tid >> 5;
    const int lane = tid & 31;
    const int ui   = w >> 1;
    const int gp   = w & 1;
    const int ug   = (ublk << 2) + ui;
    const int bb   = lane;

    // load this warp's 2 weight rows into smem (once)
    for (int g = 0; g < 2; g++) {
        int gate = gp * 2 + g;
        const float4* src = (const float4*)(whh + ((size_t)d * 1024 + gate * 256 + ug) * 256);
        float4* dst = (float4*)(wsm + (ui * 4 + gate) * 256);
        for (int i = lane; i < 64; i += 32) dst[i] = src[i];
    }

    const float4* wp0 = (const float4*)(wsm + (ui * 4 + gp * 2) * 256);
    const float4* wp1 = wp0 + 64;

    const size_t gtd = (size_t)d * T;
    float cc = 0.f;

    int t0 = (d == 0) ? 0 : (T - 1);
    size_t gb0 = ((gtd + t0) * 1024 + (size_t)(gp * 2) * 256 + ug) * 32 + bb;
    float cg0 = gt[gb0];
    float cg1 = gt[gb0 + 256 * 32];

    for (int s = 0; s < T; s++) {
        const float* hprev = hbuf + (size_t)(s & 1) * 16384;
        float* hnext       = hbuf + (size_t)((s & 1) ^ 1) * 16384;

        // stage h_prev into smem [b][k] (coalesced gmem reads)
        if (s == 0) {
            for (int idx = tid; idx < 32 * 256; idx += 256) {
                int b = idx & 31, k = idx >> 5;
                sh[b * 260 + k] = 0.f;
            }
        } else {
            for (int idx = tid; idx < 32 * 256; idx += 256) {
                int b = idx & 31, k = idx >> 5;
                sh[b * 260 + k] = hprev[(d * 256 + k) * 32 + b];
            }
        }

        // prefetch next step's gates
        float ng0 = 0.f, ng1 = 0.f;
        if (s + 1 < T) {
            int tn = (d == 0) ? (s + 1) : (T - 2 - s);
            size_t gn = ((gtd + tn) * 1024 + (size_t)(gp * 2) * 256 + ug) * 32 + bb;
            ng0 = gt[gn];
            ng1 = gt[gn + 256 * 32];
        }
        __syncthreads();

        float a0 = 0.f, a1 = 0.f;
        const float4* hv = (const float4*)(sh + bb * 260);
#pragma unroll 8
        for (int k4 = 0; k4 < 64; k4++) {
            float4 wa = wp0[k4], wb = wp1[k4];
            float4 h4 = hv[k4];
            a0 += wa.x * h4.x + wa.y * h4.y + wa.z * h4.z + wa.w * h4.w;
            a1 += wb.x * h4.x + wb.y * h4.y + wb.z * h4.z + wb.w * h4.w;
        }
        exch[ui][gp * 2 + 0][bb] = a0 + cg0;
        exch[ui][gp * 2 + 1][bb] = a1 + cg1;
        cg0 = ng0; cg1 = ng1;
        __syncthreads();

        if (gp == 0) {
            float xi = exch[ui][0][bb];
            float xf = exch[ui][1][bb];
            float xg = exch[ui][2][bb];
            float xo = exch[ui][3][bb];
            float ig = sigmoidf_(xi), fg = sigmoidf_(xf), og = sigmoidf_(xo);
            float gg = tanhf(xg);
            float cn = fg * cc + ig * gg;
            cc = cn;
            float hn = og * tanhf(cn);
            const int t = (d == 0) ? s : (T - 1 - s);
            hnext[(d * 256 + ug) * 32 + bb] = hn;
            rep[((size_t)bb * T + t) * 512 + (d << 8) + ug] = hn;
        }

        // ---- per-direction grid barrier ----
        __syncthreads();
        if (tid == 0) {
            unsigned* ctr = &g_barcnt2[d];
            asm volatile("red.release.gpu.global.add.u32 [%0], 1;" :: "l"(ctr) : "memory");
            unsigned target = 64u * (unsigned)(s + 1), v;
            do {
                asm volatile("ld.acquire.gpu.global.u32 %0, [%1];" : "=r"(v) : "l"(ctr) : "memory");
            } while (v < target);
        }
        __syncthreads();
    }
}

// ---------------- attention: uw2[r] = dot(U[r], w2) ----------------
__global__ void __launch_bounds__(256) uw2_kernel(
    const float* __restrict__ U, const float* __restrict__ attw, float* __restrict__ uw2)
{
    int w = threadIdx.x >> 5, lane = threadIdx.x & 31;
    int row = blockIdx.x * 8 + w;
    const float* w2 = attw + 512;
    float acc = 0.f;
    const float* u = U + (size_t)row * 512;
    for (int i = lane; i < 512; i += 32) acc += u[i] * w2[i];
#pragma unroll
    for (int o = 16; o; o >>= 1) acc += __shfl_xor_sync(0xffffffffu, acc, o);
    if (lane == 0) uw2[row] = acc;
}

// ---------------- attention main ----------------
__global__ void __launch_bounds__(256) attn_s(
    const float* __restrict__ Hc, const float* __restrict__ U,
    const float* __restrict__ attw, const float* __restrict__ attb,
    const float* __restrict__ uw2, float* __restrict__ G, float* __restrict__ Smax)
{
    __shared__ float hc[512], hw3[512], sS[64], wsum[8];
    __shared__ float sHw1, sMx, sSum;
    const int row = blockIdx.x;
    const int b = row >> 9;
    const int tid = threadIdx.x;
    const float* w1 = attw;
    const float* w3 = attw + 1024;
    float p0 = 0.f;
    for (int i = tid; i < 512; i += 256) {
        float v = Hc[(size_t)row * 512 + i];
        hc[i] = v; hw3[i] = v * w3[i];
        p0 += v * w1[i];
    }
#pragma unroll
    for (int o = 16; o; o >>= 1) p0 += __shfl_xor_sync(0xffffffffu, p0, o);
    int w = tid >> 5, lane = tid & 31;
    if (lane == 0) wsum[w] = p0;
    __syncthreads();
    if (tid == 0) {
        float s = 0.f;
        for (int i = 0; i < 8; i++) s += wsum[i];
        sHw1 = s;
    }
    __syncthreads();
    float bval = attb[0];
    for (int jj = 0; jj < 8; jj++) {
        int j = w * 8 + jj;
        const float* u = U + ((size_t)(b * 64 + j)) * 512;
        float acc = 0.f;
        for (int k = lane; k < 512; k += 32) acc += hw3[k] * u[k];
#pragma unroll
        for (int o = 16; o; o >>= 1) acc += __shfl_xor_sync(0xffffffffu, acc, o);
        if (lane == 0) sS[j] = sHw1 + uw2[b * 64 + j] + acc + bval;
    }
    __syncthreads();
    if (tid == 0) {
        float mx = -1e30f;
        for (int j = 0; j < 64; j++) mx = fmaxf(mx, sS[j]);
        float sm = 0.f;
        for (int j = 0; j < 64; j++) sm += expf(sS[j] - mx);
        sMx = mx; sSum = sm;
        Smax[row] = mx;
    }
    __syncthreads();
    if (tid < 64) sS[tid] = expf(sS[tid] - sMx) / sSum;
    __syncthreads();
    for (int half = 0; half < 2; half++) {
        int dc = tid + half * 256;
        float acc = 0.f;
        for (int j = 0; j < 64; j++)
            acc += sS[j] * U[((size_t)(b * 64 + j)) * 512 + dc];
        float hv = hc[dc];
        G[(size_t)row * 2048 + dc]        = hv;
        G[(size_t)row * 2048 + 512  + dc] = acc;
        G[(size_t)row * 2048 + 1024 + dc] = hv * acc;
    }
}

// ---------------- q2c ----------------
__global__ void __launch_bounds__(256) attn_q2c(
    const float* __restrict__ Smax, const float* __restrict__ Hc, float* __restrict__ q2c)
{
    __shared__ float p[512];
    __shared__ float sMx, sSum;
    const int b = blockIdx.x, tid = threadIdx.x;
    for (int i = tid; i < 512; i += 256) p[i] = Smax[b * 512 + i];
    __syncthreads();
    if (tid == 0) {
        float mx = -1e30f;
        for (int t = 0; t < 512; t++) mx = fmaxf(mx, p[t]);
        float sm = 0.f;
        for (int t = 0; t < 512; t++) sm += expf(p[t] - mx);
        sMx = mx; sSum = sm;
    }
    __syncthreads();
    for (int i = tid; i < 512; i += 256) p[i] = expf(p[i] - sMx) / sSum;
    __syncthreads();
    for (int half = 0; half < 2; half++) {
        int dc = tid + half * 256;
        float acc = 0.f;
        for (int t = 0; t < 512; t++)
            acc += p[t] * Hc[((size_t)(b * 512 + t)) * 512 + dc];
        q2c[b * 512 + dc] = acc;
    }
}

// ---------------- G[:,1536:2048] = Hc * q2c[b] ----------------
__global__ void __launch_bounds__(256) g4_kernel(
    const float* __restrict__ Hc, const float* __restrict__ q2c, float* __restrict__ G)
{
    int idx = blockIdx.x * 256 + threadIdx.x;
    if (idx >= (int)(NCs * 512)) return;
    int row = idx >> 9, dc = idx & 511;
    int b = row >> 9;
    G[(size_t)row * 2048 + 1536 + dc] = Hc[idx] * q2c[(b << 9) + dc];
}

// ---------------- final logits ----------------
__global__ void __launch_bounds__(256) final_dot(
    const float* __restrict__ G, const float* __restrict__ M,
    const float* __restrict__ pw, const float* __restrict__ pb,
    float* __restrict__ out)
{
    int w = threadIdx.x >> 5, lane = threadIdx.x & 31;
    int row = blockIdx.x * 8 + w;
    float acc = 0.f;
    const float* g = G + (size_t)row * 2048;
    for (int i = lane; i < 2048; i += 32) acc += g[i] * pw[i];
    const float* m = M + (size_t)row * 512;
    for (int i = lane; i < 512; i += 32) acc += m[i] * pw[2048 + i];
#pragma unroll
    for (int o = 16; o; o >>= 1) acc += __shfl_xor_sync(0xffffffffu, acc, o);
    if (lane == 0) out[row] = acc + pb[0];
}

// ---------------- host orchestration ----------------
static inline void launch_sgemm(const float* A, const float* Bm, float* C,
                                const float* b1, const float* b2,
                                int M, int N, int K, int relu)
{
    dim3 grid((N + 127) / 128, (M + 127) / 128);
    sgemm_tn<<<grid, 256>>>(A, Bm, C, b1, b2, M, N, K, relu);
}

extern "C" void kernel_launch(void* const* d_in, const int* in_sizes, int n_in,
                              void* d_out, int out_size)
{
    (void)in_sizes; (void)n_in; (void)out_size;
    const int*   qtok      = (const int*)d_in[0];
    const int*   ctok      = (const int*)d_in[1];
    const float* emb       = (const float*)d_in[2];
    const float* hw_lin_w  = (const float*)d_in[3];
    const float* hw_lin_b  = (const float*)d_in[4];
    const float* hw_gate_w = (const float*)d_in[5];
    const float* hw_gate_b = (const float*)d_in[6];
    const float* ctx_wih   = (const float*)d_in[7];
    const float* ctx_whh   = (const float*)d_in[8];
    const float* ctx_bih   = (const float*)d_in[9];
    const float* ctx_bhh   = (const float*)d_in[10];
    const float* mod1_wih  = (const float*)d_in[11];
    const float* mod1_whh  = (const float*)d_in[12];
    const float* mod1_bih  = (const float*)d_in[13];
    const float* mod1_bhh  = (const float*)d_in[14];
    const float* mod2_wih  = (const float*)d_in[15];
    const float* mod2_whh  = (const float*)d_in[16];
    const float* mod2_bih  = (const float*)d_in[17];
    const float* mod2_bhh  = (const float*)d_in[18];
    const float* dec_wih   = (const float*)d_in[19];
    const float* dec_whh   = (const float*)d_in[20];
    const float* dec_bih   = (const float*)d_in[21];
    const float* dec_bhh   = (const float*)d_in[22];
    const float* att_w     = (const float*)d_in[23];
    const float* att_b     = (const float*)d_in[24];
    const float* p1_w      = (const float*)d_in[25];
    const float* p1_b      = (const float*)d_in[26];
    const float* p2_w      = (const float*)d_in[27];
    const float* p2_b      = (const float*)d_in[28];
    float* out = (float*)d_out;

    float* S = nullptr;
    cudaGetSymbolAddress((void**)&S, g_scratch);
    float* cx    = S + OFF_CX;
    float* qx    = S + OFF_QX;
    float* hb    = S + OFF_HB;
    float* tb    = S + OFF_TB;
    float* crep  = S + OFF_CREP;
    float* qrep  = S + OFF_QREP;
    float* Gb    = S + OFF_G;
    float* Ma    = S + OFF_MA;
    float* Mb    = S + OFF_MB;
    float* M2b   = S + OFF_M2;
    float* gates = S + OFF_GATES;
    float* gtb   = S + OFF_GT;
    float* Hbuf  = S + OFF_H;
    float* smax  = S + OFF_SMAX;
    float* uw2b  = S + OFF_UW2;
    float* q2cb  = S + OFF_Q2C;

    const int NC = (int)NCs;
    const int NQ = (int)NQs;

    // 1. embedding gather
    gather_embed<<<(NC * E_ + 255) / 256, 256>>>(ctok, emb, cx, NC);
    gather_embed<<<(NQ * E_ + 255) / 256, 256>>>(qtok, emb, qx, NQ);

    // 2. highway (2 layers), context then question
    for (int l = 0; l < 2; l++) {
        launch_sgemm(cx, hw_lin_w + (size_t)l * E_ * E_, hb, hw_lin_b + l * E_, nullptr, NC, E_, E_, 1);
        launch_sgemm(cx, hw_gate_w + (size_t)l * E_ * E_, tb, hw_gate_b + l * E_, nullptr, NC, E_, E_, 1);
        hw_combine<<<(NC * E_ + 255) / 256, 256>>>(cx, hb, tb, NC * E_);
    }
    for (int l = 0; l < 2; l++) {
        launch_sgemm(qx, hw_lin_w + (size_t)l * E_ * E_, hb, hw_lin_b + l * E_, nullptr, NQ, E_, E_, 1);
        launch_sgemm(qx, hw_gate_w + (size_t)l * E_ * E_, tb, hw_gate_b + l * E_, nullptr, NQ, E_, E_, 1);
        hw_combine<<<(NQ * E_ + 255) / 256, 256>>>(qx, hb, tb, NQ * E_);
    }

    // one biLSTM = 1 fused gate GEMM (both dirs, N=2048) + transpose + persistent recurrence
    #define RUN_BILSTM(Xin, WIH, WHH, BIH, BHH, KDIM, ROWS, TLEN, REP)                         \
        do {                                                                                   \
            launch_sgemm((Xin), (WIH), gates, (BIH), (BHH), (ROWS), 2048, (KDIM), 0);          \
            tgates_kernel<<<dim3(8, (TLEN), 2), 256>>>(gates, gtb, (TLEN));                    \
            reset_bar<<<1, 1>>>();                                                             \
            lstm_persist<<<128, 256>>>(gtb, (WHH), Hbuf, (REP), (TLEN));                       \
        } while (0)

    // 3. contextual biLSTM
    RUN_BILSTM(cx, ctx_wih, ctx_whh, ctx_bih, ctx_bhh, E_, NC, T_, crep);
    RUN_BILSTM(qx, ctx_wih, ctx_whh, ctx_bih, ctx_bhh, E_, NQ, J_, qrep);

    // 4. attention -> G
    uw2_kernel<<<NQ / 8, 256>>>(qrep, att_w, uw2b);
    attn_s<<<NC, 256>>>(crep, qrep, att_w, att_b, uw2b, Gb, smax);
    attn_q2c<<<B_, 256>>>(smax, crep, q2cb);
    g4_kernel<<<(NC * 512 + 255) / 256, 256>>>(crep, q2cb, Gb);

    // 5. modeling biLSTMs
    RUN_BILSTM(Gb, mod1_wih, mod1_whh, mod1_bih, mod1_bhh, 2048, NC, T_, Ma);
    RUN_BILSTM(Ma, mod2_wih, mod2_whh, mod2_bih, mod2_bhh, 512, NC, T_, Mb);

    // 6. start logits
    final_dot<<<NC / 8, 256>>>(Gb, Mb, p1_w, p1_b, out);

    // 7. decode biLSTM + end logits
    RUN_BILSTM(Mb, dec_wih, dec_whh, dec_bih, dec_bhh, 512, NC, T_, M2b);
    final_dot<<<NC / 8, 256>>>(Gb, M2b, p2_w, p2_b, out + NC);

    #undef RUN_BILSTM
}